// round 16
// baseline (speedup 1.0000x reference)
#include <cuda_runtime.h>
#include <cuda_bf16.h>
#include <cstdint>
#include <cstddef>

// Problem constants
#define BB   64          // batch
#define TT   1024        // timesteps
#define DD   512         // input dim
#define HH   512         // hidden dim
#define GG   2048        // 4*H gate dim
#define NGRP 4           // independent batch groups
#define GCTA 32          // CTAs per group
#define NB   16          // batches per group
#define NCOL 16          // hidden cols per CTA
#define LCTA 128         // lstm CTAs
#define NTILE 4096       // xproj tiles (256 tblocks x 16 gate-tiles)
#define THRESH 2560      // tiles in queue-A (all CTAs); rest by spare CTAs

// ---------------- device scratch ----------------
__device__ float    g_xproj[(size_t)TT * GG * BB];  // [t][gcol][b]
__device__ float4   g_WxP[GG * DD / 4];             // Wx in mma-fragment order (k-permuted A)
__device__ float    g_Wh[GG * HH];
__device__ float    g_bsum[GG];
__device__ float    g_h[2][NGRP * NB * HH];         // per-group h, k-PERMUTED cols
__device__ unsigned g_barL[NGRP * 32];              // lo-half barrier counters (padded)
__device__ unsigned g_barH[NGRP * 32];              // hi-half barrier counters (padded)
__device__ unsigned g_wqA, g_wqB;                   // xproj tile queues
__device__ unsigned g_done[TT / 4];                 // per-tblock finished tiles

// ---------------- helpers ----------------
__device__ __forceinline__ float tf32r(float x) {
    float y; asm("cvt.rna.tf32.f32 %0, %1;" : "=f"(y) : "f"(x)); return y;
}
__device__ __forceinline__ float tanh_fast(float x) {
    float y; asm("tanh.approx.f32 %0, %1;" : "=f"(y) : "f"(x)); return y;
}
__device__ __forceinline__ float sig_fast(float x) {
    return fmaf(tanh_fast(0.5f * x), 0.5f, 0.5f);
}
__device__ __forceinline__ void mma8(float* c,
                                     unsigned a0, unsigned a1, unsigned a2, unsigned a3,
                                     unsigned b0, unsigned b1) {
    asm volatile(
        "mma.sync.aligned.m16n8k8.row.col.f32.tf32.tf32.f32 "
        "{%0,%1,%2,%3},{%4,%5,%6,%7},{%8,%9},{%0,%1,%2,%3};\n"
        : "+f"(c[0]), "+f"(c[1]), "+f"(c[2]), "+f"(c[3])
        : "r"(a0), "r"(a1), "r"(a2), "r"(a3), "r"(b0), "r"(b1));
}
__device__ __forceinline__ void mma8f(float* c, const float4& av, float2 b) {
    mma8(c, __float_as_uint(av.x), __float_as_uint(av.y),
         __float_as_uint(av.z), __float_as_uint(av.w),
         __float_as_uint(b.x), __float_as_uint(b.y));
}
__device__ __forceinline__ void cp16(float* dst, const float* src) {
    unsigned s = (unsigned)__cvta_generic_to_shared(dst);
    asm volatile("cp.async.cg.shared.global [%0], [%1], 16;\n" :: "r"(s), "l"(src));
}
#define CP_COMMIT  asm volatile("cp.async.commit_group;\n" ::: "memory")
#define CP_WAIT(N) asm volatile("cp.async.wait_group %0;\n" :: "n"(N) : "memory")

__device__ __forceinline__ void red_release(unsigned* p) {
    asm volatile("red.release.gpu.global.add.u32 [%0], %1;" :: "l"(p), "r"(1u) : "memory");
}
__device__ __forceinline__ unsigned ld_acquire(const unsigned* p) {
    unsigned v;
    asm volatile("ld.acquire.gpu.global.u32 %0, [%1];" : "=r"(v) : "l"(p) : "memory");
    return v;
}

// k-permutation within each 8-block (h exchange): true offset o -> stored offset
__device__ __host__ __forceinline__ int kperm(int o) {
    return (o < 4) ? 2 * o : 2 * (o - 4) + 1;
}

// ---------------- pack kernel ----------------
// g_WxP fragment layout: slot s = ((ctile*8 + tile)*64 + q)*32 + lane,
//   lane: lg=lane>>2 (row pair base), lt=lane&3 (k pair)
//   rows: r0 = ctile*128 + tile*16 + lg, r1 = r0+8
//   k:    k0 = q*8 + 2*lt, k1 = k0+1   (A-side k-permutation; B stays canonical)
__global__ void pack_kernel(
    const float* __restrict__ Wxf, const float* __restrict__ Wxi,
    const float* __restrict__ Wxg, const float* __restrict__ Wxo,
    const float* __restrict__ Whf, const float* __restrict__ Whi,
    const float* __restrict__ Whg, const float* __restrict__ Who,
    const float* __restrict__ bxf, const float* __restrict__ bxi,
    const float* __restrict__ bxg, const float* __restrict__ bxo,
    const float* __restrict__ bhf, const float* __restrict__ bhi,
    const float* __restrict__ bhg, const float* __restrict__ bho) {
    int i = blockIdx.x * blockDim.x + threadIdx.x;
    const float* WX[4] = {Wxf, Wxi, Wxg, Wxo};
    const float* WH[4] = {Whf, Whi, Whg, Who};
    const float* BX[4] = {bxf, bxi, bxg, bxo};
    const float* BH[4] = {bhf, bhi, bhg, bho};
    const int NP = GG * DD / 4;   // 262144 float4 slots
    const int WN = GG * DD;       // 1M
    if (i < NP) {
        int lane = i & 31, q = (i >> 5) & 63, tile = (i >> 11) & 7, ctile = i >> 14;
        int lg = lane >> 2, lt = lane & 3;
        int gr0 = ctile * 128 + tile * 16 + lg, gr1 = gr0 + 8;
        int k0 = q * 8 + 2 * lt, k1 = k0 + 1;
        int g0 = gr0 >> 9, rr0 = gr0 & 511;
        int g1 = gr1 >> 9, rr1 = gr1 & 511;
        float4 v;
        v.x = tf32r(WX[g0][rr0 * DD + k0]);
        v.y = tf32r(WX[g1][rr1 * DD + k0]);
        v.z = tf32r(WX[g0][rr0 * DD + k1]);
        v.w = tf32r(WX[g1][rr1 * DD + k1]);
        g_WxP[i] = v;
    } else if (i < NP + WN) {
        int j = i - NP;
        int row = j >> 9, col = j & 511;
        int g = row >> 9, rr = row & 511;
        g_Wh[j] = tf32r(WH[g][rr * HH + col]);
    } else if (i < NP + WN + GG) {
        int j = i - NP - WN;
        int g = j >> 9, rr = j & 511;
        g_bsum[j] = BX[g][rr] + BH[g][rr];
    }
}

__global__ void init_kernel() {
    int i = blockIdx.x * blockDim.x + threadIdx.x;
    if (i < 2 * NGRP * NB * HH) ((float*)g_h)[i] = 0.0f;
    if (i < NGRP * 32) { g_barL[i] = 0u; g_barH[i] = 0u; }
    if (i < TT / 4) g_done[i] = 0u;
    if (i == 0) { g_wqA = 0u; g_wqB = (unsigned)THRESH; }
}

// ---------------- xproj role (512 threads): one tile M=128, N=256 (4t x 64b), K=512 ----------------
// A from g_WxP (fragment order, LDS.128); B canonical raw fp32 bits, LDS.64 pairs
// (valid because A carries the matching k-permutation).
#define XP_SMEM_FLOATS (2 * 2048 * 4 + 2 * 256 * 68)   // 204800 B

__device__ void xproj_tile(float* sm, const float* __restrict__ x, int id) {
    float4* sA4 = (float4*)sm;           // [2][2048] fragment slots
    float*  sB  = sm + 2 * 2048 * 4;     // [2][256][68]
    const int tb = id >> 4;
    const int ctile = id & 15;
    const int t0 = tb * 4;
    const int tid = threadIdx.x;
    const int w = tid >> 5, lane = tid & 31;
    const int wm = w & 3, wn = w >> 2;
    const int lg = lane >> 2, lt = lane & 3;

    float acc[2][8][4];
#pragma unroll
    for (int i = 0; i < 2; i++)
#pragma unroll
        for (int j = 0; j < 8; j++)
#pragma unroll
            for (int k = 0; k < 4; k++) acc[i][j][k] = 0.0f;

    auto loadA = [&](int buf, int ch) {
        float4* dst = sA4 + buf * 2048;
#pragma unroll
        for (int j = 0; j < 4; j++) {
            int s = tid + 512 * j;               // 0..2047
            int ln = s & 31, qloc = (s >> 5) & 7, tile = s >> 8;
            const float4* src = g_WxP + ((size_t)(ctile * 8 + tile) * 64 + ch * 8 + qloc) * 32 + ln;
            cp16((float*)(dst + s), (const float*)src);
        }
    };
    auto loadB = [&](int buf, int k0) {
        float* dst = sB + buf * (256 * 68);
#pragma unroll
        for (int j = 0; j < 8; j++) {
            int l = tid + 512 * j;
            int row = l >> 4, q = l & 15;        // row = n = t'*64 + b
            int b = row & 63, tp = row >> 6;
            cp16(dst + row * 68 + q * 4,
                 x + ((size_t)b * TT + (t0 + tp)) * DD + k0 + q * 4);
        }
    };

    loadA(0, 0); loadB(0, 0); CP_COMMIT;
    for (int ch = 0; ch < 8; ch++) {
        if (ch < 7) {
            loadA((ch + 1) & 1, ch + 1);
            loadB((ch + 1) & 1, (ch + 1) * 64);
            CP_COMMIT;
            CP_WAIT(1);
        } else {
            CP_WAIT(0);
        }
        __syncthreads();
        const float4* A  = sA4 + (ch & 1) * 2048;
        const float*  Bm = sB + (ch & 1) * (256 * 68);
#pragma unroll
        for (int kk8 = 0; kk8 < 8; kk8++) {
            float4 a0 = A[((wm * 2 + 0) * 8 + kk8) * 32 + lane];
            float4 a1 = A[((wm * 2 + 1) * 8 + kk8) * 32 + lane];
#pragma unroll
            for (int ni = 0; ni < 8; ni++) {
                float2 b = *(const float2*)(Bm + (wn * 64 + ni * 8 + lg) * 68 + kk8 * 8 + 2 * lt);
                mma8f(acc[0][ni], a0, b);   // raw fp32 bits: HW tf32 truncation on B
                mma8f(acc[1][ni], a1, b);
            }
        }
        __syncthreads();
    }

    // epilogue: add (bx+bh), store [t][gcol][b]
#pragma unroll
    for (int mi = 0; mi < 2; mi++) {
#pragma unroll
        for (int rr = 0; rr < 2; rr++) {
            int gcol = ctile * 128 + wm * 32 + mi * 16 + rr * 8 + lg;
            float bs = g_bsum[gcol];
#pragma unroll
            for (int ni = 0; ni < 8; ni++) {
                int n = wn * 64 + ni * 8 + 2 * lt;
                int b = n & 63, tp = n >> 6;
                float2 v = make_float2(acc[mi][ni][2 * rr + 0] + bs,
                                       acc[mi][ni][2 * rr + 1] + bs);
                *(float2*)&g_xproj[(((size_t)(t0 + tp)) * GG + gcol) * BB + b] = v;
            }
        }
    }
    __syncthreads();   // all stores issued before the release below
    if (tid == 0) red_release(&g_done[tb]);
}

// ---------------- lstm role (512 threads, Wh in registers, split-half barrier) ----------------
// 128 CTAs. group = bid>>5 (16 batches), r = bid&31 (16 hidden cols).
// CTAs r<16 produce h cols 0..255 (barL); r>=16 produce cols 256..511 (barH).
// 16 warps: gt = w&3 (gate m16), kq = w>>2 (K-quarter). kq 0,1 run after lo lands;
// kq 2,3 after hi lands (overlapping hi transfer with lo MMA).
#define SH_STRIDE 520
#define SG_STRIDE 18

__device__ void lstm_role(float* sm, float* __restrict__ out, int bid) {
    float* sH = sm;                        // [16][520] (k-permuted cols)
    float* sG = sm + NB * SH_STRIDE;       // [4 kq][64][18]
    const int group = bid >> 5;
    const int r     = bid & 31;
    const int tid = threadIdx.x;
    const int w = tid >> 5, lane = tid & 31;
    const int lg = lane >> 2, lt = lane & 3;
    const int gt = w & 3;                  // gate index (m16 tile)
    const int kq = w >> 2;                 // K-quarter

    // ---- load my A fragments (Wh, tf32-rounded, canonical k pairs (lt, lt+4)) ----
    float4 av[16];
    {
        const int row0 = gt * 512 + r * NCOL + lg;
        const int row1 = row0 + 8;
#pragma unroll
        for (int q = 0; q < 16; q++) {
            int cc0 = kq * 128 + q * 8 + lt, cc1 = cc0 + 4;
            av[q].x = g_Wh[(size_t)row0 * HH + cc0];
            av[q].y = g_Wh[(size_t)row1 * HH + cc0];
            av[q].z = g_Wh[(size_t)row0 * HH + cc1];
            av[q].w = g_Wh[(size_t)row1 * HH + cc1];
        }
    }

    // cell-update ownership (threads 0-255): 1 cell per thread
    const int jl = (tid >> 4) & 15;
    const int bl = tid & 15;
    const int jglob = r * NCOL + jl;
    const int bglob = group * NB + bl;
    const int pj = (jglob & ~7) | kperm(jglob & 7);
    float cst = 0.0f;

    float4 xc = make_float4(0.f, 0.f, 0.f, 0.f), xn = xc;
    auto ldxp = [&](int tt) {
        const float* base = g_xproj + (size_t)tt * GG * BB;
        float4 v;
        v.x = base[(size_t)(0 * 512 + jglob) * BB + bglob];
        v.y = base[(size_t)(1 * 512 + jglob) * BB + bglob];
        v.z = base[(size_t)(2 * 512 + jglob) * BB + bglob];
        v.w = base[(size_t)(3 * 512 + jglob) * BB + bglob];
        return v;
    };
    // wait for xproj tblock 0, then load step-0 xproj
    if (tid == 0) { while (ld_acquire(&g_done[0]) < 16u) {} }
    __syncthreads();
    if (tid < 256) xc = ldxp(0);
    __syncthreads();

    const float* bP0 = sH + (0 + lg) * SH_STRIDE + kq * 128 + 2 * lt;
    const float* bP1 = sH + (8 + lg) * SH_STRIDE + kq * 128 + 2 * lt;
    float* sGq = sG + kq * 64 * SG_STRIDE;
    unsigned* barL = &g_barL[group * 32];
    unsigned* barH = &g_barH[group * 32];
    unsigned* mybar = (r < 16) ? barL : barH;

    for (int t = 0; t < TT; t++) {
        const float* hsrc = g_h[t & 1] + (size_t)group * NB * HH;
        float*       hdst = g_h[(t & 1) ^ 1] + (size_t)group * NB * HH;
        const unsigned tgt = (unsigned)t * 16u;

        // -- lo half: wait producers r<16, stage cols 0..255 --
        if (tid == 0) { while (ld_acquire(barL) < tgt) {} }
        __syncthreads();
#pragma unroll
        for (int j = 0; j < 2; j++) {
            int e = tid + 512 * j;                 // 0..1023
            int row = e >> 6, q = e & 63;
            cp16(sH + row * SH_STRIDE + q * 4, hsrc + (size_t)row * HH + q * 4);
        }
        CP_COMMIT;

        // -- hi half: wait producers r>=16 (overlaps lo flight), plus xproj boundary poll --
        if (tid == 0) {
            if (t + 1 < TT && ((t + 1) & 3) == 0) {
                int tb = (t + 1) >> 2;
                while (ld_acquire(&g_done[tb]) < 16u) {}
            }
            while (ld_acquire(barH) < tgt) {}
        }
        __syncthreads();
#pragma unroll
        for (int j = 0; j < 2; j++) {
            int e = tid + 512 * j;
            int row = e >> 6, q = e & 63;
            cp16(sH + row * SH_STRIDE + 256 + q * 4, hsrc + (size_t)row * HH + 256 + q * 4);
        }
        CP_COMMIT;

        // prefetch next step's xproj during MMA phase
        if (t + 1 < TT && tid < 256) xn = ldxp(t + 1);

        CP_WAIT(1);                                 // lo staged
        asm volatile("bar.sync 1, 512;" ::: "memory");
        if (kq < 2) {                               // lo-K warps run while hi lands
            float acc[2][4];
#pragma unroll
            for (int a = 0; a < 2; a++)
#pragma unroll
                for (int d = 0; d < 4; d++) acc[a][d] = 0.0f;
#pragma unroll
            for (int q = 0; q < 16; q++) {
                float2 b0 = *(const float2*)(bP0 + q * 8);
                float2 b1 = *(const float2*)(bP1 + q * 8);
                mma8f(acc[0], av[q], b0);
                mma8f(acc[1], av[q], b1);
            }
#pragma unroll
            for (int nt = 0; nt < 2; nt++) {
                int nb0 = nt * 8 + 2 * lt;
                *(float2*)&sGq[(gt * 16 + lg) * SG_STRIDE + nb0] =
                    make_float2(acc[nt][0], acc[nt][1]);
                *(float2*)&sGq[(gt * 16 + lg + 8) * SG_STRIDE + nb0] =
                    make_float2(acc[nt][2], acc[nt][3]);
            }
        }
        CP_WAIT(0);                                 // hi staged
        asm volatile("bar.sync 2, 512;" ::: "memory");
        if (kq >= 2) {
            float acc[2][4];
#pragma unroll
            for (int a = 0; a < 2; a++)
#pragma unroll
                for (int d = 0; d < 4; d++) acc[a][d] = 0.0f;
#pragma unroll
            for (int q = 0; q < 16; q++) {
                float2 b0 = *(const float2*)(bP0 + q * 8);
                float2 b1 = *(const float2*)(bP1 + q * 8);
                mma8f(acc[0], av[q], b0);
                mma8f(acc[1], av[q], b1);
            }
#pragma unroll
            for (int nt = 0; nt < 2; nt++) {
                int nb0 = nt * 8 + 2 * lt;
                *(float2*)&sGq[(gt * 16 + lg) * SG_STRIDE + nb0] =
                    make_float2(acc[nt][0], acc[nt][1]);
                *(float2*)&sGq[(gt * 16 + lg + 8) * SG_STRIDE + nb0] =
                    make_float2(acc[nt][2], acc[nt][3]);
            }
        }
        __syncthreads();

        // cell update (threads 0-255, 1 cell each): merge 4 K-quarters
        if (tid < 256) {
            const int Q = 64 * SG_STRIDE;
            float fv = xc.x, iv = xc.y, gv = xc.z, ov = xc.w;
#pragma unroll
            for (int qq = 0; qq < 4; qq++) {
                fv += sG[qq * Q + (0 * 16 + jl) * SG_STRIDE + bl];
                iv += sG[qq * Q + (1 * 16 + jl) * SG_STRIDE + bl];
                gv += sG[qq * Q + (2 * 16 + jl) * SG_STRIDE + bl];
                ov += sG[qq * Q + (3 * 16 + jl) * SG_STRIDE + bl];
            }
            float f_ = sig_fast(fv);
            float i_ = sig_fast(iv);
            float g_ = tanh_fast(gv);
            float o_ = sig_fast(ov);
            cst = f_ * cst + i_ * g_;
            float h_ = o_ * tanh_fast(cst);
            hdst[(size_t)bl * HH + pj] = tf32r(h_);
            if (t == TT - 1) out[(size_t)bglob * HH + jglob] = h_;
            xc = xn;
        }

        // arrive on MY half-counter (after all h stores in this CTA are done)
        __syncthreads();
        if (tid == 0) red_release(mybar);
    }
}

// ---------------- fused persistent kernel ----------------
__global__ void __launch_bounds__(512, 1) fused_kernel(float* __restrict__ out,
                                                       const float* __restrict__ x) {
    extern __shared__ float sm[];
    __shared__ unsigned s_tile;
    // Phase A: all CTAs drain queue-A (tiles 0..THRESH)
    while (true) {
        if (threadIdx.x == 0) s_tile = atomicAdd(&g_wqA, 1u);
        __syncthreads();
        unsigned id = s_tile;
        if (id >= THRESH) break;
        xproj_tile(sm, x, (int)id);
        __syncthreads();
    }
    __syncthreads();

    if (blockIdx.x < LCTA) {
        lstm_role(sm, out, blockIdx.x);
    } else {
        // Phase B: spare CTAs drain queue-B (tiles THRESH..NTILE)
        while (true) {
            if (threadIdx.x == 0) s_tile = atomicAdd(&g_wqB, 1u);
            __syncthreads();
            unsigned id = s_tile;
            if (id >= NTILE) break;
            xproj_tile(sm, x, (int)id);
            __syncthreads();
        }
    }
}

// ---------------- launcher ----------------
extern "C" void kernel_launch(void* const* d_in, const int* in_sizes, int n_in,
                              void* d_out, int out_size) {
    const float* x   = (const float*)d_in[0];
    const float* Whf = (const float*)d_in[1];  const float* bhf = (const float*)d_in[2];
    const float* Wxf = (const float*)d_in[3];  const float* bxf = (const float*)d_in[4];
    const float* Whi = (const float*)d_in[5];  const float* bhi = (const float*)d_in[6];
    const float* Wxi = (const float*)d_in[7];  const float* bxi = (const float*)d_in[8];
    const float* Whg = (const float*)d_in[9];  const float* bhg = (const float*)d_in[10];
    const float* Wxg = (const float*)d_in[11]; const float* bxg = (const float*)d_in[12];
    const float* Who = (const float*)d_in[13]; const float* bho = (const float*)d_in[14];
    const float* Wxo = (const float*)d_in[15]; const float* bxo = (const float*)d_in[16];

    const int fused_smem = XP_SMEM_FLOATS * 4;   // 204800 B (covers both roles)
    cudaFuncSetAttribute(fused_kernel, cudaFuncAttributeMaxDynamicSharedMemorySize, fused_smem);

    int packN = GG * DD / 4 + GG * DD + GG;
    pack_kernel<<<(packN + 255) / 256, 256>>>(Wxf, Wxi, Wxg, Wxo,
                                              Whf, Whi, Whg, Who,
                                              bxf, bxi, bxg, bxo,
                                              bhf, bhi, bhg, bho);
    init_kernel<<<(2 * NGRP * NB * HH + 255) / 256, 256>>>();

    fused_kernel<<<148, 512, fused_smem>>>((float*)d_out, x);
}

// round 17
// speedup vs baseline: 1.1190x; 1.1190x over previous
#include <cuda_runtime.h>
#include <cuda_bf16.h>
#include <cstdint>
#include <cstddef>

// Problem constants
#define BB   64          // batch
#define TT   1024        // timesteps
#define DD   512         // input dim
#define HH   512         // hidden dim
#define GG   2048        // 4*H gate dim
#define NGRP 4           // independent batch groups
#define GCTA 32          // CTAs per group
#define NB   16          // batches per group
#define NCOL 16          // hidden cols per CTA
#define LCTA 128         // lstm CTAs
#define NTILE 4096       // xproj tiles (256 tblocks x 16 gate-tiles)
#define THRESH 2560      // tiles in queue-A (all CTAs); rest by spare CTAs

// ---------------- device scratch ----------------
__device__ float    g_xproj[(size_t)TT * GG * BB];  // [t][gcol][b]
__device__ float4   g_WxP[GG * DD / 4];             // Wx in mma-fragment order (k-permuted A)
__device__ float    g_Wh[GG * HH];
__device__ float    g_bsum[GG];
__device__ float    g_h[2][NGRP * NB * HH];         // per-group h, k-PERMUTED cols
__device__ unsigned g_bar4[NGRP * 32];              // padded barrier counters
__device__ unsigned g_wqA, g_wqB;                   // xproj tile queues
__device__ unsigned g_done[TT / 4];                 // per-tblock finished tiles

// ---------------- helpers ----------------
__device__ __forceinline__ float tf32r(float x) {
    float y; asm("cvt.rna.tf32.f32 %0, %1;" : "=f"(y) : "f"(x)); return y;
}
__device__ __forceinline__ float tanh_fast(float x) {
    float y; asm("tanh.approx.f32 %0, %1;" : "=f"(y) : "f"(x)); return y;
}
__device__ __forceinline__ float sig_fast(float x) {
    return fmaf(tanh_fast(0.5f * x), 0.5f, 0.5f);
}
__device__ __forceinline__ void mma8(float* c,
                                     unsigned a0, unsigned a1, unsigned a2, unsigned a3,
                                     unsigned b0, unsigned b1) {
    asm volatile(
        "mma.sync.aligned.m16n8k8.row.col.f32.tf32.tf32.f32 "
        "{%0,%1,%2,%3},{%4,%5,%6,%7},{%8,%9},{%0,%1,%2,%3};\n"
        : "+f"(c[0]), "+f"(c[1]), "+f"(c[2]), "+f"(c[3])
        : "r"(a0), "r"(a1), "r"(a2), "r"(a3), "r"(b0), "r"(b1));
}
__device__ __forceinline__ void mma8f(float* c, const float4& av, float2 b) {
    mma8(c, __float_as_uint(av.x), __float_as_uint(av.y),
         __float_as_uint(av.z), __float_as_uint(av.w),
         __float_as_uint(b.x), __float_as_uint(b.y));
}
__device__ __forceinline__ void cp16(float* dst, const float* src) {
    unsigned s = (unsigned)__cvta_generic_to_shared(dst);
    asm volatile("cp.async.cg.shared.global [%0], [%1], 16;\n" :: "r"(s), "l"(src));
}
#define CP_COMMIT  asm volatile("cp.async.commit_group;\n" ::: "memory")
#define CP_WAIT(N) asm volatile("cp.async.wait_group %0;\n" :: "n"(N) : "memory")

__device__ __forceinline__ void red_release(unsigned* p) {
    asm volatile("red.release.gpu.global.add.u32 [%0], %1;" :: "l"(p), "r"(1u) : "memory");
}
__device__ __forceinline__ unsigned ld_acquire(const unsigned* p) {
    unsigned v;
    asm volatile("ld.acquire.gpu.global.u32 %0, [%1];" : "=r"(v) : "l"(p) : "memory");
    return v;
}

// k-permutation within each 8-block (h exchange): true offset o -> stored offset
__device__ __host__ __forceinline__ int kperm(int o) {
    return (o < 4) ? 2 * o : 2 * (o - 4) + 1;
}

// ---------------- pack kernel ----------------
// g_WxP fragment layout: slot s = ((ctile*8 + tile)*64 + q)*32 + lane,
//   lane: lg=lane>>2 (row pair base), lt=lane&3 (k pair)
//   rows: r0 = ctile*128 + tile*16 + lg, r1 = r0+8
//   k:    k0 = q*8 + 2*lt, k1 = k0+1   (A-side k-permutation; B stays canonical)
__global__ void pack_kernel(
    const float* __restrict__ Wxf, const float* __restrict__ Wxi,
    const float* __restrict__ Wxg, const float* __restrict__ Wxo,
    const float* __restrict__ Whf, const float* __restrict__ Whi,
    const float* __restrict__ Whg, const float* __restrict__ Who,
    const float* __restrict__ bxf, const float* __restrict__ bxi,
    const float* __restrict__ bxg, const float* __restrict__ bxo,
    const float* __restrict__ bhf, const float* __restrict__ bhi,
    const float* __restrict__ bhg, const float* __restrict__ bho) {
    int i = blockIdx.x * blockDim.x + threadIdx.x;
    const float* WX[4] = {Wxf, Wxi, Wxg, Wxo};
    const float* WH[4] = {Whf, Whi, Whg, Who};
    const float* BX[4] = {bxf, bxi, bxg, bxo};
    const float* BH[4] = {bhf, bhi, bhg, bho};
    const int NP = GG * DD / 4;   // 262144 float4 slots
    const int WN = GG * DD;       // 1M
    if (i < NP) {
        int lane = i & 31, q = (i >> 5) & 63, tile = (i >> 11) & 7, ctile = i >> 14;
        int lg = lane >> 2, lt = lane & 3;
        int gr0 = ctile * 128 + tile * 16 + lg, gr1 = gr0 + 8;
        int k0 = q * 8 + 2 * lt, k1 = k0 + 1;
        int g0 = gr0 >> 9, rr0 = gr0 & 511;
        int g1 = gr1 >> 9, rr1 = gr1 & 511;
        float4 v;
        v.x = tf32r(WX[g0][rr0 * DD + k0]);
        v.y = tf32r(WX[g1][rr1 * DD + k0]);
        v.z = tf32r(WX[g0][rr0 * DD + k1]);
        v.w = tf32r(WX[g1][rr1 * DD + k1]);
        g_WxP[i] = v;
    } else if (i < NP + WN) {
        int j = i - NP;
        int row = j >> 9, col = j & 511;
        int g = row >> 9, rr = row & 511;
        g_Wh[j] = tf32r(WH[g][rr * HH + col]);
    } else if (i < NP + WN + GG) {
        int j = i - NP - WN;
        int g = j >> 9, rr = j & 511;
        g_bsum[j] = BX[g][rr] + BH[g][rr];
    }
}

__global__ void init_kernel() {
    int i = blockIdx.x * blockDim.x + threadIdx.x;
    if (i < 2 * NGRP * NB * HH) ((float*)g_h)[i] = 0.0f;
    if (i < NGRP * 32) g_bar4[i] = 0u;
    if (i < TT / 4) g_done[i] = 0u;
    if (i == 0) { g_wqA = 0u; g_wqB = (unsigned)THRESH; }
}

// ---------------- xproj role (512 threads): one tile M=128, N=256 (4t x 64b), K=512 ----------------
// A from g_WxP (fragment order, LDS.128); B canonical raw fp32 bits, LDS.64 pairs
// (valid because A carries the matching k-permutation).
#define XP_SMEM_FLOATS (2 * 2048 * 4 + 2 * 256 * 68)   // 204800 B

__device__ void xproj_tile(float* sm, const float* __restrict__ x, int id) {
    float4* sA4 = (float4*)sm;           // [2][2048] fragment slots
    float*  sB  = sm + 2 * 2048 * 4;     // [2][256][68]
    const int tb = id >> 4;
    const int ctile = id & 15;
    const int t0 = tb * 4;
    const int tid = threadIdx.x;
    const int w = tid >> 5, lane = tid & 31;
    const int wm = w & 3, wn = w >> 2;
    const int lg = lane >> 2, lt = lane & 3;

    float acc[2][8][4];
#pragma unroll
    for (int i = 0; i < 2; i++)
#pragma unroll
        for (int j = 0; j < 8; j++)
#pragma unroll
            for (int k = 0; k < 4; k++) acc[i][j][k] = 0.0f;

    auto loadA = [&](int buf, int ch) {
        float4* dst = sA4 + buf * 2048;
#pragma unroll
        for (int j = 0; j < 4; j++) {
            int s = tid + 512 * j;               // 0..2047
            int ln = s & 31, qloc = (s >> 5) & 7, tile = s >> 8;
            const float4* src = g_WxP + ((size_t)(ctile * 8 + tile) * 64 + ch * 8 + qloc) * 32 + ln;
            cp16((float*)(dst + s), (const float*)src);
        }
    };
    auto loadB = [&](int buf, int k0) {
        float* dst = sB + buf * (256 * 68);
#pragma unroll
        for (int j = 0; j < 8; j++) {
            int l = tid + 512 * j;
            int row = l >> 4, q = l & 15;        // row = n = t'*64 + b
            int b = row & 63, tp = row >> 6;
            cp16(dst + row * 68 + q * 4,
                 x + ((size_t)b * TT + (t0 + tp)) * DD + k0 + q * 4);
        }
    };

    loadA(0, 0); loadB(0, 0); CP_COMMIT;
    for (int ch = 0; ch < 8; ch++) {
        if (ch < 7) {
            loadA((ch + 1) & 1, ch + 1);
            loadB((ch + 1) & 1, (ch + 1) * 64);
            CP_COMMIT;
            CP_WAIT(1);
        } else {
            CP_WAIT(0);
        }
        __syncthreads();
        const float4* A  = sA4 + (ch & 1) * 2048;
        const float*  Bm = sB + (ch & 1) * (256 * 68);
#pragma unroll
        for (int kk8 = 0; kk8 < 8; kk8++) {
            float4 a0 = A[((wm * 2 + 0) * 8 + kk8) * 32 + lane];
            float4 a1 = A[((wm * 2 + 1) * 8 + kk8) * 32 + lane];
#pragma unroll
            for (int ni = 0; ni < 8; ni++) {
                float2 b = *(const float2*)(Bm + (wn * 64 + ni * 8 + lg) * 68 + kk8 * 8 + 2 * lt);
                mma8f(acc[0][ni], a0, b);   // raw fp32 bits: HW tf32 truncation on B
                mma8f(acc[1][ni], a1, b);
            }
        }
        __syncthreads();
    }

    // epilogue: add (bx+bh), store [t][gcol][b]
#pragma unroll
    for (int mi = 0; mi < 2; mi++) {
#pragma unroll
        for (int rr = 0; rr < 2; rr++) {
            int gcol = ctile * 128 + wm * 32 + mi * 16 + rr * 8 + lg;
            float bs = g_bsum[gcol];
#pragma unroll
            for (int ni = 0; ni < 8; ni++) {
                int n = wn * 64 + ni * 8 + 2 * lt;
                int b = n & 63, tp = n >> 6;
                float2 v = make_float2(acc[mi][ni][2 * rr + 0] + bs,
                                       acc[mi][ni][2 * rr + 1] + bs);
                *(float2*)&g_xproj[(((size_t)(t0 + tp)) * GG + gcol) * BB + b] = v;
            }
        }
    }
    __syncthreads();   // all stores issued before the release below
    if (tid == 0) red_release(&g_done[tb]);
}

// ---------------- lstm role (512 threads, Wh in registers) — R12 structure ----------------
// 128 CTAs. group = bid>>5 (16 batches), r = bid&31 (16 hidden cols).
// Per CTA: M = 64 gate rows, N = 16 batches, K = 512.
// 16 warps: gt = w&3 (gate m16), kq = w>>2 (K-quarter 128).
// A fragments held in registers. Staging halves by tid>>8, single group barrier.
#define SH_STRIDE 520
#define SG_STRIDE 18

__device__ void lstm_role(float* sm, float* __restrict__ out, int bid) {
    float* sH = sm;                        // [16][520] (k-permuted cols)
    float* sG = sm + NB * SH_STRIDE;       // [4 kq][64][18]
    const int group = bid >> 5;
    const int r     = bid & 31;
    const int tid = threadIdx.x;
    const int w = tid >> 5, lane = tid & 31;
    const int lg = lane >> 2, lt = lane & 3;
    const int gt = w & 3;                  // gate index (m16 tile)
    const int kq = w >> 2;                 // K-quarter
    const int half = tid >> 8;             // staging half (cols 0-255 / 256-511)
    const int ltid = tid & 255;

    // ---- load my A fragments (Wh, tf32-rounded) into registers: 16 float4 ----
    float4 av[16];
    {
        const int row0 = gt * 512 + r * NCOL + lg;
        const int row1 = row0 + 8;
#pragma unroll
        for (int q = 0; q < 16; q++) {
            int cc0 = kq * 128 + q * 8 + lt, cc1 = cc0 + 4;
            av[q].x = g_Wh[(size_t)row0 * HH + cc0];
            av[q].y = g_Wh[(size_t)row1 * HH + cc0];
            av[q].z = g_Wh[(size_t)row0 * HH + cc1];
            av[q].w = g_Wh[(size_t)row1 * HH + cc1];
        }
    }

    // cell-update ownership (threads 0-255): 1 cell per thread
    const int jl = (tid >> 4) & 15;
    const int bl = tid & 15;
    const int jglob = r * NCOL + jl;
    const int bglob = group * NB + bl;
    const int pj = (jglob & ~7) | kperm(jglob & 7);
    float cst = 0.0f;

    float4 xc = make_float4(0.f, 0.f, 0.f, 0.f), xn = xc;
    auto ldxp = [&](int tt) {
        const float* base = g_xproj + (size_t)tt * GG * BB;
        float4 v;
        v.x = base[(size_t)(0 * 512 + jglob) * BB + bglob];
        v.y = base[(size_t)(1 * 512 + jglob) * BB + bglob];
        v.z = base[(size_t)(2 * 512 + jglob) * BB + bglob];
        v.w = base[(size_t)(3 * 512 + jglob) * BB + bglob];
        return v;
    };
    // wait for xproj tblock 0, then load step-0 xproj
    if (tid == 0) { while (ld_acquire(&g_done[0]) < 16u) {} }
    __syncthreads();
    if (tid < 256) xc = ldxp(0);
    __syncthreads();

    const float* bP0 = sH + (0 + lg) * SH_STRIDE + kq * 128 + 2 * lt;
    const float* bP1 = sH + (8 + lg) * SH_STRIDE + kq * 128 + 2 * lt;
    float* sGq = sG + kq * 64 * SG_STRIDE;
    unsigned* mybar = &g_bar4[group * 32];

    for (int t = 0; t < TT; t++) {
        const float* hsrc = g_h[t & 1] + (size_t)group * NB * HH;
        float*       hdst = g_h[(t & 1) ^ 1] + (size_t)group * NB * HH;

        // stage my half of h (16 rows x 256 cols f32): 4 cp16/thread
#pragma unroll
        for (int j = 0; j < 4; j++) {
            int e = ltid + 256 * j;
            int row = e >> 6, q = e & 63;
            cp16(sH + row * SH_STRIDE + half * 256 + q * 4,
                 hsrc + (size_t)row * HH + half * 256 + q * 4);
        }
        CP_COMMIT;

        // prefetch next step's xproj (producer poll only at tblock boundary)
        if (t + 1 < TT) {
            if (((t + 1) & 3) == 0) {
                int tb = (t + 1) >> 2;
                if (tid == 0) { while (ld_acquire(&g_done[tb]) < 16u) {} }
                __syncthreads();
            }
            if (tid < 256) xn = ldxp(t + 1);
        }

        CP_WAIT(0);
        // my half fully staged once all 256 threads of my half pass this barrier
        asm volatile("bar.sync %0, 256;" :: "r"(1 + half) : "memory");

        // warp MMA: m16 x n16 over K-quarter kq (16 k-steps), A in registers
        {
            float acc[2][4];
#pragma unroll
            for (int a = 0; a < 2; a++)
#pragma unroll
                for (int d = 0; d < 4; d++) acc[a][d] = 0.0f;

#pragma unroll
            for (int q = 0; q < 16; q++) {
                float2 b0 = *(const float2*)(bP0 + q * 8);
                float2 b1 = *(const float2*)(bP1 + q * 8);
                mma8f(acc[0], av[q], b0);
                mma8f(acc[1], av[q], b1);
            }

#pragma unroll
            for (int nt = 0; nt < 2; nt++) {
                int nb0 = nt * 8 + 2 * lt;
                *(float2*)&sGq[(gt * 16 + lg) * SG_STRIDE + nb0] =
                    make_float2(acc[nt][0], acc[nt][1]);
                *(float2*)&sGq[(gt * 16 + lg + 8) * SG_STRIDE + nb0] =
                    make_float2(acc[nt][2], acc[nt][3]);
            }
        }
        __syncthreads();

        // cell update (threads 0-255, 1 cell each): merge 4 K-quarters
        if (tid < 256) {
            const int Q = 64 * SG_STRIDE;
            float fv = xc.x, iv = xc.y, gv = xc.z, ov = xc.w;
#pragma unroll
            for (int qq = 0; qq < 4; qq++) {
                fv += sG[qq * Q + (0 * 16 + jl) * SG_STRIDE + bl];
                iv += sG[qq * Q + (1 * 16 + jl) * SG_STRIDE + bl];
                gv += sG[qq * Q + (2 * 16 + jl) * SG_STRIDE + bl];
                ov += sG[qq * Q + (3 * 16 + jl) * SG_STRIDE + bl];
            }
            float f_ = sig_fast(fv);
            float i_ = sig_fast(iv);
            float g_ = tanh_fast(gv);
            float o_ = sig_fast(ov);
            cst = f_ * cst + i_ * g_;
            float h_ = o_ * tanh_fast(cst);
            hdst[(size_t)bl * HH + pj] = tf32r(h_);
            if (t == TT - 1) out[(size_t)bglob * HH + jglob] = h_;
            xc = xn;
        }

        // group barrier: tid0 arrives + polls, CTA-wide broadcast via syncthreads
        __syncthreads();
        if (tid == 0) {
            red_release(mybar);
            unsigned target = (unsigned)(t + 1) * GCTA;
            while (ld_acquire(mybar) < target) {}
        }
        __syncthreads();
    }
}

// ---------------- fused persistent kernel ----------------
__global__ void __launch_bounds__(512, 1) fused_kernel(float* __restrict__ out,
                                                       const float* __restrict__ x) {
    extern __shared__ float sm[];
    __shared__ unsigned s_tile;
    // Phase A: all CTAs drain queue-A (tiles 0..THRESH)
    while (true) {
        if (threadIdx.x == 0) s_tile = atomicAdd(&g_wqA, 1u);
        __syncthreads();
        unsigned id = s_tile;
        if (id >= THRESH) break;
        xproj_tile(sm, x, (int)id);
        __syncthreads();
    }
    __syncthreads();

    if (blockIdx.x < LCTA) {
        lstm_role(sm, out, blockIdx.x);
    } else {
        // Phase B: spare CTAs drain queue-B (tiles THRESH..NTILE)
        while (true) {
            if (threadIdx.x == 0) s_tile = atomicAdd(&g_wqB, 1u);
            __syncthreads();
            unsigned id = s_tile;
            if (id >= NTILE) break;
            xproj_tile(sm, x, (int)id);
            __syncthreads();
        }
    }
}

// ---------------- launcher ----------------
extern "C" void kernel_launch(void* const* d_in, const int* in_sizes, int n_in,
                              void* d_out, int out_size) {
    const float* x   = (const float*)d_in[0];
    const float* Whf = (const float*)d_in[1];  const float* bhf = (const float*)d_in[2];
    const float* Wxf = (const float*)d_in[3];  const float* bxf = (const float*)d_in[4];
    const float* Whi = (const float*)d_in[5];  const float* bhi = (const float*)d_in[6];
    const float* Wxi = (const float*)d_in[7];  const float* bxi = (const float*)d_in[8];
    const float* Whg = (const float*)d_in[9];  const float* bhg = (const float*)d_in[10];
    const float* Wxg = (const float*)d_in[11]; const float* bxg = (const float*)d_in[12];
    const float* Who = (const float*)d_in[13]; const float* bho = (const float*)d_in[14];
    const float* Wxo = (const float*)d_in[15]; const float* bxo = (const float*)d_in[16];

    const int fused_smem = XP_SMEM_FLOATS * 4;   // 204800 B (covers both roles)
    cudaFuncSetAttribute(fused_kernel, cudaFuncAttributeMaxDynamicSharedMemorySize, fused_smem);

    int packN = GG * DD / 4 + GG * DD + GG;
    pack_kernel<<<(packN + 255) / 256, 256>>>(Wxf, Wxi, Wxg, Wxo,
                                              Whf, Whi, Whg, Who,
                                              bxf, bxi, bxg, bxo,
                                              bhf, bhi, bhg, bho);
    init_kernel<<<(2 * NGRP * NB * HH + 255) / 256, 256>>>();

    fused_kernel<<<148, 512, fused_smem>>>((float*)d_out, x);
}